// round 3
// baseline (speedup 1.0000x reference)
#include <cuda_runtime.h>

#define NN 50000
#define EE 800000
#define FULL 0xffffffffu

// ---------------- scratch (static device globals; no allocs) ----------------
static __device__ float g_h[NN*64];      // GCN-transformed features
static __device__ float g_res[NN*64];    // residual branch
static __device__ float g_xln[NN*64];    // post-GCN layernorm output
static __device__ float g_xg[NN*64];     // GAT-transformed features
static __device__ float g_xcur[NN*64];   // layer-0 output
static __device__ float g_deg[NN];
static __device__ float g_dinv[NN];
static __device__ int   g_cnt[NN];       // in-degree counts (edges only)
static __device__ int   g_ps[NN];        // inclusive scan scratch
static __device__ int   g_blk[128];      // block sums
static __device__ int   g_blkoff[128];
static __device__ int   g_rowptr[NN+1];
static __device__ int   g_cur[NN];
static __device__ int   g_csrc[EE];      // CSR source node per slot
static __device__ int   g_cdst[EE];      // CSR dst node per slot
static __device__ float g_cw[EE];        // CSR gcn norm weight per slot
static __device__ float g_cea[EE];       // CSR edge_attr per slot
static __device__ float g_as[NN*4];
static __device__ float g_ad[NN*4];
static __device__ float g_ep[EE*4];      // exp(alpha) per CSR slot, 4 heads
static __device__ float g_ce[8];         // [0..3]=ce per head, [4]=mean(edge_attr)
static __device__ float g_easum;

// ---------------- helpers ----------------
__device__ __forceinline__ float siluf(float v) { return v * (1.f / (1.f + __expf(-v))); }
__device__ __forceinline__ float lrelu(float v) { return v >= 0.f ? v : 0.2f * v; }

// ---------------- GEMMs ----------------
// g_h = x@W0, g_res = x@W1 + b1. 32-row tile, 256 threads.
__global__ __launch_bounds__(256) void k_gemm_dual(
    const float* __restrict__ xin, const float* __restrict__ W0,
    const float* __restrict__ W1, const float* __restrict__ b1)
{
    const float* x = xin ? xin : g_xcur;
    __shared__ float xs[32*68];
    __shared__ float ws[2][64*68];
    int t = threadIdx.x;
    int row0 = blockIdx.x * 32;
    for (int i = t; i < 4096; i += 256) {
        int k = i >> 6, c = i & 63;
        ws[0][k*68+c] = W0[i];
        ws[1][k*68+c] = W1[i];
    }
    for (int i = t; i < 2048; i += 256) {
        int r = i >> 6, c = i & 63;
        xs[r*68+c] = (row0 + r < NN) ? x[(row0+r)*64 + c] : 0.f;
    }
    __syncthreads();
    int rg = t >> 4, g = t & 15, m = g >> 3, cb = (g & 7) * 8;
    const float* wp = ws[m];
    int r0 = rg*2, r1 = r0 + 1;
    float a0[8], a1[8];
    #pragma unroll
    for (int j = 0; j < 8; j++) { a0[j] = 0.f; a1[j] = 0.f; }
    #pragma unroll 16
    for (int k = 0; k < 64; k++) {
        float xv0 = xs[r0*68+k], xv1 = xs[r1*68+k];
        float w[8];
        *(float4*)&w[0] = *(const float4*)&wp[k*68+cb];
        *(float4*)&w[4] = *(const float4*)&wp[k*68+cb+4];
        #pragma unroll
        for (int j = 0; j < 8; j++) { a0[j] += xv0 * w[j]; a1[j] += xv1 * w[j]; }
    }
    float* y = m ? g_res : g_h;
    if (m) {
        #pragma unroll
        for (int j = 0; j < 8; j++) { float b = b1[cb+j]; a0[j] += b; a1[j] += b; }
    }
    if (row0 + r0 < NN) {
        *(float4*)&y[(row0+r0)*64+cb]   = *(float4*)&a0[0];
        *(float4*)&y[(row0+r0)*64+cb+4] = *(float4*)&a0[4];
    }
    if (row0 + r1 < NN) {
        *(float4*)&y[(row0+r1)*64+cb]   = *(float4*)&a1[0];
        *(float4*)&y[(row0+r1)*64+cb+4] = *(float4*)&a1[4];
    }
}

// g_xg = g_xln @ W ; fused attention dots g_as/g_ad. 64-row tile, 256 threads.
__global__ __launch_bounds__(256) void k_gemm_gat(
    const float* __restrict__ W,
    const float* __restrict__ asrc, const float* __restrict__ adst)
{
    __shared__ float xs[64*68];
    __shared__ float ws[64*68];
    int t = threadIdx.x;
    int row0 = blockIdx.x * 64;
    for (int i = t; i < 4096; i += 256) {
        int k = i >> 6, c = i & 63;
        ws[k*68+c] = W[i];
    }
    for (int i = t; i < 4096; i += 256) {
        int r = i >> 6, c = i & 63;
        xs[r*68+c] = (row0 + r < NN) ? g_xln[(row0+r)*64 + c] : 0.f;
    }
    __syncthreads();
    int rg = t >> 3, cb = (t & 7) * 8;
    int r0 = rg*2, r1 = r0 + 1;
    float a0[8], a1[8];
    #pragma unroll
    for (int j = 0; j < 8; j++) { a0[j] = 0.f; a1[j] = 0.f; }
    #pragma unroll 16
    for (int k = 0; k < 64; k++) {
        float xv0 = xs[r0*68+k], xv1 = xs[r1*68+k];
        float w[8];
        *(float4*)&w[0] = *(const float4*)&ws[k*68+cb];
        *(float4*)&w[4] = *(const float4*)&ws[k*68+cb+4];
        #pragma unroll
        for (int j = 0; j < 8; j++) { a0[j] += xv0 * w[j]; a1[j] += xv1 * w[j]; }
    }
    if (row0 + r0 < NN) {
        *(float4*)&g_xg[(row0+r0)*64+cb]   = *(float4*)&a0[0];
        *(float4*)&g_xg[(row0+r0)*64+cb+4] = *(float4*)&a0[4];
    }
    if (row0 + r1 < NN) {
        *(float4*)&g_xg[(row0+r1)*64+cb]   = *(float4*)&a1[0];
        *(float4*)&g_xg[(row0+r1)*64+cb+4] = *(float4*)&a1[4];
    }
    // fused attention dots: thread pair (t, t^1) covers one head (16 cols)
    float s0 = 0.f, s1 = 0.f, d0 = 0.f, d1 = 0.f;
    #pragma unroll
    for (int j = 0; j < 8; j++) {
        float av = asrc[cb+j], dv = adst[cb+j];
        s0 += a0[j]*av; d0 += a0[j]*dv;
        s1 += a1[j]*av; d1 += a1[j]*dv;
    }
    s0 += __shfl_xor_sync(FULL, s0, 1);
    s1 += __shfl_xor_sync(FULL, s1, 1);
    d0 += __shfl_xor_sync(FULL, d0, 1);
    d1 += __shfl_xor_sync(FULL, d1, 1);
    if ((t & 1) == 0) {
        int hh = cb >> 4;
        if (row0 + r0 < NN) { g_as[(row0+r0)*4+hh] = s0; g_ad[(row0+r0)*4+hh] = d0; }
        if (row0 + r1 < NN) { g_as[(row0+r1)*4+hh] = s1; g_ad[(row0+r1)*4+hh] = d1; }
    }
}

// ---------------- graph setup (once per call) ----------------
__global__ void k_zero() { g_easum = 0.f; }
__global__ void k_easum(const float* __restrict__ ea) {
    __shared__ float ss[8];
    float sum = 0.f;
    for (int i = blockIdx.x*blockDim.x + threadIdx.x; i < EE; i += gridDim.x*blockDim.x)
        sum += ea[i];
    #pragma unroll
    for (int o = 16; o; o >>= 1) sum += __shfl_xor_sync(FULL, sum, o);
    if ((threadIdx.x & 31) == 0) ss[threadIdx.x >> 5] = sum;
    __syncthreads();
    if (threadIdx.x < 8) {
        float v = ss[threadIdx.x];
        #pragma unroll
        for (int o = 4; o; o >>= 1) v += __shfl_xor_sync(0xffu, v, o);
        if (threadIdx.x == 0) atomicAdd(&g_easum, v);
    }
}
__global__ void k_deg_init() {
    int i = blockIdx.x*256 + threadIdx.x;
    if (i < NN) { g_deg[i] = 1.f; g_cnt[i] = 0; }
}
__global__ void k_deg_edge(const int* __restrict__ ei, const float* __restrict__ ew) {
    int e = blockIdx.x*256 + threadIdx.x;
    int d = ei[EE+e];
    atomicAdd(&g_deg[d], ew[e]);
    atomicAdd(&g_cnt[d], 1);
}
__global__ void k_dinv() {
    int i = blockIdx.x*256 + threadIdx.x;
    if (i < NN) g_dinv[i] = rsqrtf(g_deg[i]);
}
__global__ __launch_bounds__(512) void k_scan1() {
    __shared__ int sm[512];
    int t = threadIdx.x;
    int idx = blockIdx.x*512 + t;
    int c = (idx < NN) ? g_cnt[idx] : 0;
    sm[t] = c; __syncthreads();
    #pragma unroll
    for (int off = 1; off < 512; off <<= 1) {
        int v = (t >= off) ? sm[t-off] : 0;
        __syncthreads();
        sm[t] += v;
        __syncthreads();
    }
    if (idx < NN) g_ps[idx] = sm[t];
    if (t == 511) g_blk[blockIdx.x] = sm[511];
}
__global__ void k_scan2(int nblk) {
    if (threadIdx.x == 0) {
        int run = 0;
        for (int i = 0; i < nblk; i++) { g_blkoff[i] = run; run += g_blk[i]; }
    }
}
__global__ __launch_bounds__(512) void k_scan3() {
    int idx = blockIdx.x*512 + threadIdx.x;
    if (idx < NN) {
        g_rowptr[idx+1] = g_ps[idx] + g_blkoff[blockIdx.x];
        g_cur[idx] = 0;
        if (idx == 0) g_rowptr[0] = 0;
    }
}
__global__ void k_fill(const int* __restrict__ ei, const float* __restrict__ ew,
                       const float* __restrict__ ea) {
    int e = blockIdx.x*256 + threadIdx.x;
    int s = ei[e], d = ei[EE+e];
    int pos = g_rowptr[d] + atomicAdd(&g_cur[d], 1);
    g_csrc[pos] = s;
    g_cdst[pos] = d;
    g_cw[pos]   = g_dinv[s] * ew[e] * g_dinv[d];
    g_cea[pos]  = ea[e];
}

// ---------------- GCN gather + silu + residual + LN (warp per node) ----------------
__global__ __launch_bounds__(256) void k_gcn_ln(
    const float* __restrict__ gb, const float* __restrict__ lg, const float* __restrict__ lb)
{
    int row = blockIdx.x*8 + (threadIdx.x >> 5);
    if (row >= NN) return;
    int lane = threadIdx.x & 31;
    int start = g_rowptr[row], end = g_rowptr[row+1];
    float dv = g_dinv[row];
    float acc0 = g_h[row*64+lane]    * dv * dv;
    float acc1 = g_h[row*64+32+lane] * dv * dv;
    for (int base = start; base < end; base += 32) {
        int j = base + lane;
        int ms  = (j < end) ? g_csrc[j] : 0;
        float mw = (j < end) ? g_cw[j] : 0.f;
        int n = min(32, end - base);
        int k = 0;
        for (; k + 4 <= n; k += 4) {
            int s0 = __shfl_sync(FULL, ms, k),   s1 = __shfl_sync(FULL, ms, k+1);
            int s2 = __shfl_sync(FULL, ms, k+2), s3 = __shfl_sync(FULL, ms, k+3);
            float w0 = __shfl_sync(FULL, mw, k),   w1 = __shfl_sync(FULL, mw, k+1);
            float w2 = __shfl_sync(FULL, mw, k+2), w3 = __shfl_sync(FULL, mw, k+3);
            float a0 = g_h[s0*64+lane],    a1 = g_h[s1*64+lane];
            float a2 = g_h[s2*64+lane],    a3 = g_h[s3*64+lane];
            float b0 = g_h[s0*64+32+lane], b1 = g_h[s1*64+32+lane];
            float b2 = g_h[s2*64+32+lane], b3 = g_h[s3*64+32+lane];
            acc0 += w0*a0; acc0 += w1*a1; acc0 += w2*a2; acc0 += w3*a3;
            acc1 += w0*b0; acc1 += w1*b1; acc1 += w2*b2; acc1 += w3*b3;
        }
        for (; k < n; k++) {
            int s  = __shfl_sync(FULL, ms, k);
            float w = __shfl_sync(FULL, mw, k);
            acc0 += w * g_h[s*64+lane];
            acc1 += w * g_h[s*64+32+lane];
        }
    }
    float v0 = siluf(acc0 + gb[lane])    + g_res[row*64+lane];
    float v1 = siluf(acc1 + gb[lane+32]) + g_res[row*64+32+lane];
    float sum = v0 + v1;
    #pragma unroll
    for (int o = 16; o; o >>= 1) sum += __shfl_xor_sync(FULL, sum, o);
    float mu = sum * (1.f/64.f);
    float d0 = v0 - mu, d1 = v1 - mu;
    float vs = d0*d0 + d1*d1;
    #pragma unroll
    for (int o = 16; o; o >>= 1) vs += __shfl_xor_sync(FULL, vs, o);
    float inv = rsqrtf(vs * (1.f/64.f) + 1e-5f);
    g_xln[row*64+lane]    = d0 * inv * lg[lane]    + lb[lane];
    g_xln[row*64+32+lane] = d1 * inv * lg[lane+32] + lb[lane+32];
}

// ---------------- GAT ----------------
// ce[h] = sum_c We[h*16+c]*a_e[h*16+c]; ce[4] = mean(edge_attr)
__global__ void k_ce(const float* __restrict__ eww, const float* __restrict__ ae) {
    int lane = threadIdx.x;
    float p0 = eww[lane]*ae[lane];
    float p1 = eww[lane+32]*ae[lane+32];
    #pragma unroll
    for (int o = 8; o; o >>= 1) {
        p0 += __shfl_xor_sync(FULL, p0, o);
        p1 += __shfl_xor_sync(FULL, p1, o);
    }
    if ((lane & 15) == 0) {
        g_ce[lane >> 4]       = p0;
        g_ce[2 + (lane >> 4)] = p1;
    }
    if (lane == 0) g_ce[4] = g_easum * (1.f / EE);
}
// CSR-ordered edge-parallel: exp(alpha) written linearly
__global__ void k_gatA() {
    int e = blockIdx.x*256 + threadIdx.x;   // CSR slot
    int s = g_csrc[e], d = g_cdst[e];
    float eav = g_cea[e];
    float4 av = *(const float4*)&g_as[s*4];
    float4 dv = *(const float4*)&g_ad[d*4];
    float4 ce = *(const float4*)&g_ce[0];
    float4 p;
    p.x = __expf(fminf(lrelu(av.x + dv.x + eav*ce.x), 70.f));
    p.y = __expf(fminf(lrelu(av.y + dv.y + eav*ce.y), 70.f));
    p.z = __expf(fminf(lrelu(av.z + dv.z + eav*ce.z), 70.f));
    p.w = __expf(fminf(lrelu(av.w + dv.w + eav*ce.w), 70.f));
    *(float4*)&g_ep[e*4] = p;
}
// warp-per-node: softmax denom + weighted gather + silu + skip
__global__ __launch_bounds__(256) void k_gat_gather(
    const float* __restrict__ bg, float* __restrict__ xout)
{
    int row = blockIdx.x*8 + (threadIdx.x >> 5);
    if (row >= NN) return;
    int lane = threadIdx.x & 31;
    int start = g_rowptr[row], end = g_rowptr[row+1];
    // self-loop exp(alpha)
    float4 av = *(const float4*)&g_as[row*4];
    float4 dv = *(const float4*)&g_ad[row*4];
    float4 ce = *(const float4*)&g_ce[0];
    float cm = g_ce[4];
    float4 ps;
    ps.x = __expf(fminf(lrelu(av.x + dv.x + cm*ce.x), 70.f));
    ps.y = __expf(fminf(lrelu(av.y + dv.y + cm*ce.y), 70.f));
    ps.z = __expf(fminf(lrelu(av.z + dv.z + cm*ce.z), 70.f));
    ps.w = __expf(fminf(lrelu(av.w + dv.w + cm*ce.w), 70.f));
    // denominator: lane-parallel sum of g_ep
    float s0 = 0.f, s1 = 0.f, s2 = 0.f, s3 = 0.f;
    for (int j = start + lane; j < end; j += 32) {
        float4 p = *(const float4*)&g_ep[j*4];
        s0 += p.x; s1 += p.y; s2 += p.z; s3 += p.w;
    }
    #pragma unroll
    for (int o = 16; o; o >>= 1) {
        s0 += __shfl_xor_sync(FULL, s0, o);
        s1 += __shfl_xor_sync(FULL, s1, o);
        s2 += __shfl_xor_sync(FULL, s2, o);
        s3 += __shfl_xor_sync(FULL, s3, o);
    }
    float i0 = 1.f/(ps.x + s0 + 1e-16f);
    float i1 = 1.f/(ps.y + s1 + 1e-16f);
    float i2 = 1.f/(ps.z + s2 + 1e-16f);
    float i3 = 1.f/(ps.w + s3 + 1e-16f);
    // accumulate: col c=lane uses head lane>>4 (0/1); col c=lane+32 uses head 2+(lane>>4)
    float pa_self = (lane < 16) ? ps.x : ps.y;
    float pb_self = (lane < 16) ? ps.z : ps.w;
    float acc0 = g_xg[row*64+lane]    * pa_self;
    float acc1 = g_xg[row*64+32+lane] * pb_self;
    for (int base = start; base < end; base += 32) {
        int j = base + lane;
        int ms = (j < end) ? g_csrc[j] : 0;
        float4 mp = (j < end) ? *(const float4*)&g_ep[j*4] : make_float4(0.f,0.f,0.f,0.f);
        int n = min(32, end - base);
        int k = 0;
        for (; k + 2 <= n; k += 2) {
            int sA = __shfl_sync(FULL, ms, k);
            int sB = __shfl_sync(FULL, ms, k+1);
            float pA0 = __shfl_sync(FULL, mp.x, k), pA1 = __shfl_sync(FULL, mp.y, k);
            float pA2 = __shfl_sync(FULL, mp.z, k), pA3 = __shfl_sync(FULL, mp.w, k);
            float pB0 = __shfl_sync(FULL, mp.x, k+1), pB1 = __shfl_sync(FULL, mp.y, k+1);
            float pB2 = __shfl_sync(FULL, mp.z, k+1), pB3 = __shfl_sync(FULL, mp.w, k+1);
            float aA = g_xg[sA*64+lane],    aB = g_xg[sB*64+lane];
            float bA = g_xg[sA*64+32+lane], bB = g_xg[sB*64+32+lane];
            float paA = (lane < 16) ? pA0 : pA1;
            float pbA = (lane < 16) ? pA2 : pA3;
            float paB = (lane < 16) ? pB0 : pB1;
            float pbB = (lane < 16) ? pB2 : pB3;
            acc0 += paA * aA; acc0 += paB * aB;
            acc1 += pbA * bA; acc1 += pbB * bB;
        }
        for (; k < n; k++) {
            int s = __shfl_sync(FULL, ms, k);
            float p0 = __shfl_sync(FULL, mp.x, k);
            float p1 = __shfl_sync(FULL, mp.y, k);
            float p2 = __shfl_sync(FULL, mp.z, k);
            float p3 = __shfl_sync(FULL, mp.w, k);
            float pa = (lane < 16) ? p0 : p1;
            float pb = (lane < 16) ? p2 : p3;
            acc0 += pa * g_xg[s*64+lane];
            acc1 += pb * g_xg[s*64+32+lane];
        }
    }
    float ia = (lane < 16) ? i0 : i1;
    float ib = (lane < 16) ? i2 : i3;
    float* o = xout ? xout : g_xcur;
    o[row*64+lane]    = siluf(acc0*ia + bg[lane])    + g_xln[row*64+lane];
    o[row*64+32+lane] = siluf(acc1*ib + bg[lane+32]) + g_xln[row*64+32+lane];
}

// ---------------- launch ----------------
extern "C" void kernel_launch(void* const* d_in, const int* in_sizes, int n_in,
                              void* d_out, int out_size) {
    (void)in_sizes; (void)n_in; (void)out_size;
    const float* x  = (const float*)d_in[0];
    const int*   ei = (const int*)  d_in[1];
    const float* ew = (const float*)d_in[2];
    const float* ea = (const float*)d_in[3];

    // graph-structure setup (layer-independent)
    k_zero<<<1,1>>>();
    k_easum<<<1024,256>>>(ea);
    k_deg_init<<<196,256>>>();
    k_deg_edge<<<3125,256>>>(ei, ew);
    k_dinv<<<196,256>>>();
    k_scan1<<<98,512>>>();
    k_scan2<<<1,32>>>(98);
    k_scan3<<<98,512>>>();
    k_fill<<<3125,256>>>(ei, ew, ea);

    for (int L = 0; L < 2; L++) {
        const float* gw  = (const float*)d_in[4+12*L+0];
        const float* gb  = (const float*)d_in[4+12*L+1];
        const float* rw  = (const float*)d_in[4+12*L+2];
        const float* rb  = (const float*)d_in[4+12*L+3];
        const float* lg  = (const float*)d_in[4+12*L+4];
        const float* lb  = (const float*)d_in[4+12*L+5];
        const float* Wg  = (const float*)d_in[4+12*L+6];
        const float* bg  = (const float*)d_in[4+12*L+7];
        const float* asv = (const float*)d_in[4+12*L+8];
        const float* adv = (const float*)d_in[4+12*L+9];
        const float* aev = (const float*)d_in[4+12*L+10];
        const float* eww = (const float*)d_in[4+12*L+11];

        const float* xin  = (L == 0) ? x : nullptr;             // null -> g_xcur
        float*       xout = (L == 1) ? (float*)d_out : nullptr; // null -> g_xcur

        k_gemm_dual<<<1563,256>>>(xin, gw, rw, rb);
        k_gcn_ln<<<6250,256>>>(gb, lg, lb);
        k_gemm_gat<<<782,256>>>(Wg, asv, adv);
        k_ce<<<1,32>>>(eww, aev);
        k_gatA<<<3125,256>>>();
        k_gat_gather<<<6250,256>>>(bg, xout);
    }
}

// round 4
// speedup vs baseline: 1.3383x; 1.3383x over previous
#include <cuda_runtime.h>

#define NN 50000
#define EE 800000
#define FULL 0xffffffffu

// ---------------- scratch (static device globals; no allocs) ----------------
static __device__ float g_h[NN*64];      // GCN-transformed features
static __device__ float g_res[NN*64];    // residual branch
static __device__ float g_xln[NN*64];    // post-GCN layernorm output
static __device__ float g_xg[NN*64];     // GAT-transformed features
static __device__ float g_xcur[NN*64];   // layer-0 output
static __device__ float g_deg[NN];
static __device__ float g_dinv[NN];
static __device__ int   g_cnt[NN];       // in-degree counts (edges only)
static __device__ int   g_ps[NN];        // inclusive scan scratch
static __device__ int   g_blk[128];      // block sums
static __device__ int   g_blkoff[128];
static __device__ int   g_rowptr[NN+1];
static __device__ int   g_cur[NN];
static __device__ int   g_csrc[EE];      // CSR source node per slot
static __device__ float g_cw[EE];        // CSR gcn norm weight per slot
static __device__ float g_cea[EE];       // CSR edge_attr per slot
static __device__ float g_as[NN*4];
static __device__ float g_ad[NN*4];
static __device__ float g_ce[8];         // [0..3]=ce per head, [4]=mean(edge_attr)
static __device__ float g_easum;

// ---------------- helpers ----------------
__device__ __forceinline__ float siluf(float v) { return v * (1.f / (1.f + __expf(-v))); }
__device__ __forceinline__ float lrelu(float v) { return v >= 0.f ? v : 0.2f * v; }

// ---------------- GEMMs ----------------
// g_h = x@W0, g_res = x@W1 + b1. 32-row tile, 256 threads.
__global__ __launch_bounds__(256) void k_gemm_dual(
    const float* __restrict__ xin, const float* __restrict__ W0,
    const float* __restrict__ W1, const float* __restrict__ b1)
{
    const float* x = xin ? xin : g_xcur;
    __shared__ float xs[32*68];
    __shared__ float ws[2][64*68];
    int t = threadIdx.x;
    int row0 = blockIdx.x * 32;
    for (int i = t; i < 4096; i += 256) {
        int k = i >> 6, c = i & 63;
        ws[0][k*68+c] = W0[i];
        ws[1][k*68+c] = W1[i];
    }
    for (int i = t; i < 2048; i += 256) {
        int r = i >> 6, c = i & 63;
        xs[r*68+c] = (row0 + r < NN) ? x[(row0+r)*64 + c] : 0.f;
    }
    __syncthreads();
    int rg = t >> 4, g = t & 15, m = g >> 3, cb = (g & 7) * 8;
    const float* wp = ws[m];
    int r0 = rg*2, r1 = r0 + 1;
    float a0[8], a1[8];
    #pragma unroll
    for (int j = 0; j < 8; j++) { a0[j] = 0.f; a1[j] = 0.f; }
    #pragma unroll 16
    for (int k = 0; k < 64; k++) {
        float xv0 = xs[r0*68+k], xv1 = xs[r1*68+k];
        float w[8];
        *(float4*)&w[0] = *(const float4*)&wp[k*68+cb];
        *(float4*)&w[4] = *(const float4*)&wp[k*68+cb+4];
        #pragma unroll
        for (int j = 0; j < 8; j++) { a0[j] += xv0 * w[j]; a1[j] += xv1 * w[j]; }
    }
    float* y = m ? g_res : g_h;
    if (m) {
        #pragma unroll
        for (int j = 0; j < 8; j++) { float b = b1[cb+j]; a0[j] += b; a1[j] += b; }
    }
    if (row0 + r0 < NN) {
        *(float4*)&y[(row0+r0)*64+cb]   = *(float4*)&a0[0];
        *(float4*)&y[(row0+r0)*64+cb+4] = *(float4*)&a0[4];
    }
    if (row0 + r1 < NN) {
        *(float4*)&y[(row0+r1)*64+cb]   = *(float4*)&a1[0];
        *(float4*)&y[(row0+r1)*64+cb+4] = *(float4*)&a1[4];
    }
}

// g_xg = g_xln @ W ; fused attention dots g_as/g_ad. 64-row tile, 256 threads.
__global__ __launch_bounds__(256) void k_gemm_gat(
    const float* __restrict__ W,
    const float* __restrict__ asrc, const float* __restrict__ adst)
{
    __shared__ float xs[64*68];
    __shared__ float ws[64*68];
    int t = threadIdx.x;
    int row0 = blockIdx.x * 64;
    for (int i = t; i < 4096; i += 256) {
        int k = i >> 6, c = i & 63;
        ws[k*68+c] = W[i];
    }
    for (int i = t; i < 4096; i += 256) {
        int r = i >> 6, c = i & 63;
        xs[r*68+c] = (row0 + r < NN) ? g_xln[(row0+r)*64 + c] : 0.f;
    }
    __syncthreads();
    int rg = t >> 3, cb = (t & 7) * 8;
    int r0 = rg*2, r1 = r0 + 1;
    float a0[8], a1[8];
    #pragma unroll
    for (int j = 0; j < 8; j++) { a0[j] = 0.f; a1[j] = 0.f; }
    #pragma unroll 16
    for (int k = 0; k < 64; k++) {
        float xv0 = xs[r0*68+k], xv1 = xs[r1*68+k];
        float w[8];
        *(float4*)&w[0] = *(const float4*)&ws[k*68+cb];
        *(float4*)&w[4] = *(const float4*)&ws[k*68+cb+4];
        #pragma unroll
        for (int j = 0; j < 8; j++) { a0[j] += xv0 * w[j]; a1[j] += xv1 * w[j]; }
    }
    if (row0 + r0 < NN) {
        *(float4*)&g_xg[(row0+r0)*64+cb]   = *(float4*)&a0[0];
        *(float4*)&g_xg[(row0+r0)*64+cb+4] = *(float4*)&a0[4];
    }
    if (row0 + r1 < NN) {
        *(float4*)&g_xg[(row0+r1)*64+cb]   = *(float4*)&a1[0];
        *(float4*)&g_xg[(row0+r1)*64+cb+4] = *(float4*)&a1[4];
    }
    // fused attention dots: thread pair (t, t^1) covers one head (16 cols)
    float s0 = 0.f, s1 = 0.f, d0 = 0.f, d1 = 0.f;
    #pragma unroll
    for (int j = 0; j < 8; j++) {
        float av = asrc[cb+j], dv = adst[cb+j];
        s0 += a0[j]*av; d0 += a0[j]*dv;
        s1 += a1[j]*av; d1 += a1[j]*dv;
    }
    s0 += __shfl_xor_sync(FULL, s0, 1);
    s1 += __shfl_xor_sync(FULL, s1, 1);
    d0 += __shfl_xor_sync(FULL, d0, 1);
    d1 += __shfl_xor_sync(FULL, d1, 1);
    if ((t & 1) == 0) {
        int hh = cb >> 4;
        if (row0 + r0 < NN) { g_as[(row0+r0)*4+hh] = s0; g_ad[(row0+r0)*4+hh] = d0; }
        if (row0 + r1 < NN) { g_as[(row0+r1)*4+hh] = s1; g_ad[(row0+r1)*4+hh] = d1; }
    }
}

// ---------------- graph setup (once per call) ----------------
__global__ void k_init() {
    int i = blockIdx.x*256 + threadIdx.x;
    if (i < NN) { g_deg[i] = 1.f; g_cnt[i] = 0; }
    if (i == 0) g_easum = 0.f;
}
__global__ void k_easum(const float* __restrict__ ea) {
    __shared__ float ss[8];
    float sum = 0.f;
    for (int i = blockIdx.x*blockDim.x + threadIdx.x; i < EE; i += gridDim.x*blockDim.x)
        sum += ea[i];
    #pragma unroll
    for (int o = 16; o; o >>= 1) sum += __shfl_xor_sync(FULL, sum, o);
    if ((threadIdx.x & 31) == 0) ss[threadIdx.x >> 5] = sum;
    __syncthreads();
    if (threadIdx.x < 8) {
        float v = ss[threadIdx.x];
        #pragma unroll
        for (int o = 4; o; o >>= 1) v += __shfl_xor_sync(0xffu, v, o);
        if (threadIdx.x == 0) atomicAdd(&g_easum, v);
    }
}
__global__ void k_deg_edge(const int* __restrict__ ei, const float* __restrict__ ew) {
    int e = blockIdx.x*256 + threadIdx.x;
    int d = ei[EE+e];
    atomicAdd(&g_deg[d], ew[e]);
    atomicAdd(&g_cnt[d], 1);
}
__global__ __launch_bounds__(512) void k_scan1() {
    __shared__ int sm[512];
    int t = threadIdx.x;
    int idx = blockIdx.x*512 + t;
    if (idx < NN) g_dinv[idx] = rsqrtf(g_deg[idx]);
    int c = (idx < NN) ? g_cnt[idx] : 0;
    sm[t] = c; __syncthreads();
    #pragma unroll
    for (int off = 1; off < 512; off <<= 1) {
        int v = (t >= off) ? sm[t-off] : 0;
        __syncthreads();
        sm[t] += v;
        __syncthreads();
    }
    if (idx < NN) g_ps[idx] = sm[t];
    if (t == 511) g_blk[blockIdx.x] = sm[511];
}
__global__ void k_scan2(int nblk) {
    if (threadIdx.x == 0) {
        int run = 0;
        for (int i = 0; i < nblk; i++) { g_blkoff[i] = run; run += g_blk[i]; }
    }
}
__global__ __launch_bounds__(512) void k_scan3() {
    int idx = blockIdx.x*512 + threadIdx.x;
    if (idx < NN) {
        g_rowptr[idx+1] = g_ps[idx] + g_blkoff[blockIdx.x];
        g_cur[idx] = 0;
        if (idx == 0) g_rowptr[0] = 0;
    }
}
__global__ void k_fill(const int* __restrict__ ei, const float* __restrict__ ew,
                       const float* __restrict__ ea) {
    int e = blockIdx.x*256 + threadIdx.x;
    int s = ei[e], d = ei[EE+e];
    int pos = g_rowptr[d] + atomicAdd(&g_cur[d], 1);
    g_csrc[pos] = s;
    g_cw[pos]   = g_dinv[s] * ew[e] * g_dinv[d];
    g_cea[pos]  = ea[e];
}

// ---------------- GCN gather + silu + residual + LN (warp per node) ----------------
__global__ __launch_bounds__(256) void k_gcn_ln(
    const float* __restrict__ gb, const float* __restrict__ lg, const float* __restrict__ lb)
{
    int row = blockIdx.x*8 + (threadIdx.x >> 5);
    if (row >= NN) return;
    int lane = threadIdx.x & 31;
    int start = g_rowptr[row], end = g_rowptr[row+1];
    float dv = g_dinv[row];
    float acc0 = g_h[row*64+lane]    * dv * dv;
    float acc1 = g_h[row*64+32+lane] * dv * dv;
    for (int base = start; base < end; base += 32) {
        int j = base + lane;
        int ms  = (j < end) ? g_csrc[j] : 0;
        float mw = (j < end) ? g_cw[j] : 0.f;
        int n = min(32, end - base);
        for (int k = 0; k < n; k++) {
            int s  = __shfl_sync(FULL, ms, k);
            float w = __shfl_sync(FULL, mw, k);
            acc0 += w * __ldg(&g_h[s*64+lane]);
            acc1 += w * __ldg(&g_h[s*64+32+lane]);
        }
    }
    float v0 = siluf(acc0 + gb[lane])    + g_res[row*64+lane];
    float v1 = siluf(acc1 + gb[lane+32]) + g_res[row*64+32+lane];
    float sum = v0 + v1;
    #pragma unroll
    for (int o = 16; o; o >>= 1) sum += __shfl_xor_sync(FULL, sum, o);
    float mu = sum * (1.f/64.f);
    float d0 = v0 - mu, d1 = v1 - mu;
    float vs = d0*d0 + d1*d1;
    #pragma unroll
    for (int o = 16; o; o >>= 1) vs += __shfl_xor_sync(FULL, vs, o);
    float inv = rsqrtf(vs * (1.f/64.f) + 1e-5f);
    g_xln[row*64+lane]    = d0 * inv * lg[lane]    + lb[lane];
    g_xln[row*64+32+lane] = d1 * inv * lg[lane+32] + lb[lane+32];
}

// ---------------- GAT ----------------
// ce[h] = sum_c We[h*16+c]*a_e[h*16+c]; ce[4] = mean(edge_attr)
__global__ void k_ce(const float* __restrict__ eww, const float* __restrict__ ae) {
    int lane = threadIdx.x;
    float p0 = eww[lane]*ae[lane];
    float p1 = eww[lane+32]*ae[lane+32];
    #pragma unroll
    for (int o = 8; o; o >>= 1) {
        p0 += __shfl_xor_sync(FULL, p0, o);
        p1 += __shfl_xor_sync(FULL, p1, o);
    }
    if ((lane & 15) == 0) {
        g_ce[lane >> 4]       = p0;
        g_ce[2 + (lane >> 4)] = p1;
    }
    if (lane == 0) g_ce[4] = g_easum * (1.f / EE);
}

// warp-per-node: fused alpha + softmax (single pass) + weighted gather + silu + skip
__global__ __launch_bounds__(256) void k_gat_gather(
    const float* __restrict__ bg, float* __restrict__ xout)
{
    int row = blockIdx.x*8 + (threadIdx.x >> 5);
    if (row >= NN) return;
    int lane = threadIdx.x & 31;
    int start = g_rowptr[row], end = g_rowptr[row+1];
    float4 ad4 = *(const float4*)&g_ad[row*4];
    float4 ce4 = *(const float4*)&g_ce[0];
    float cm = g_ce[4];
    // self-loop exp(alpha)
    float4 av = *(const float4*)&g_as[row*4];
    float4 ps;
    ps.x = __expf(fminf(lrelu(av.x + ad4.x + cm*ce4.x), 70.f));
    ps.y = __expf(fminf(lrelu(av.y + ad4.y + cm*ce4.y), 70.f));
    ps.z = __expf(fminf(lrelu(av.z + ad4.z + cm*ce4.z), 70.f));
    ps.w = __expf(fminf(lrelu(av.w + ad4.w + cm*ce4.w), 70.f));
    float pa_self = (lane < 16) ? ps.x : ps.y;
    float pb_self = (lane < 16) ? ps.z : ps.w;
    float acc0 = g_xg[row*64+lane]    * pa_self;
    float acc1 = g_xg[row*64+32+lane] * pb_self;
    float sa = pa_self, sb = pb_self;        // per-lane softmax denominators
    for (int base = start; base < end; base += 32) {
        int j = base + lane;
        int ms = (j < end) ? g_csrc[j] : 0;
        float eav = (j < end) ? g_cea[j] : 0.f;
        float4 asv = (j < end) ? *(const float4*)&g_as[ms*4]
                               : make_float4(0.f,0.f,0.f,0.f);
        float4 p;
        p.x = __expf(fminf(lrelu(asv.x + ad4.x + eav*ce4.x), 70.f));
        p.y = __expf(fminf(lrelu(asv.y + ad4.y + eav*ce4.y), 70.f));
        p.z = __expf(fminf(lrelu(asv.z + ad4.z + eav*ce4.z), 70.f));
        p.w = __expf(fminf(lrelu(asv.w + ad4.w + eav*ce4.w), 70.f));
        int n = min(32, end - base);
        for (int k = 0; k < n; k++) {
            int s = __shfl_sync(FULL, ms, k);
            float p0 = __shfl_sync(FULL, p.x, k);
            float p1 = __shfl_sync(FULL, p.y, k);
            float p2 = __shfl_sync(FULL, p.z, k);
            float p3 = __shfl_sync(FULL, p.w, k);
            float pa = (lane < 16) ? p0 : p1;
            float pb = (lane < 16) ? p2 : p3;
            acc0 += pa * __ldg(&g_xg[s*64+lane]);
            acc1 += pb * __ldg(&g_xg[s*64+32+lane]);
            sa += pa;
            sb += pb;
        }
    }
    float ia = 1.f/(sa + 1e-16f);
    float ib = 1.f/(sb + 1e-16f);
    float* o = xout ? xout : g_xcur;
    o[row*64+lane]    = siluf(acc0*ia + bg[lane])    + g_xln[row*64+lane];
    o[row*64+32+lane] = siluf(acc1*ib + bg[lane+32]) + g_xln[row*64+32+lane];
}

// ---------------- launch ----------------
extern "C" void kernel_launch(void* const* d_in, const int* in_sizes, int n_in,
                              void* d_out, int out_size) {
    (void)in_sizes; (void)n_in; (void)out_size;
    const float* x  = (const float*)d_in[0];
    const int*   ei = (const int*)  d_in[1];
    const float* ew = (const float*)d_in[2];
    const float* ea = (const float*)d_in[3];

    // graph-structure setup (layer-independent)
    k_init<<<196,256>>>();
    k_easum<<<1024,256>>>(ea);
    k_deg_edge<<<3125,256>>>(ei, ew);
    k_scan1<<<98,512>>>();
    k_scan2<<<1,32>>>(98);
    k_scan3<<<98,512>>>();
    k_fill<<<3125,256>>>(ei, ew, ea);

    for (int L = 0; L < 2; L++) {
        const float* gw  = (const float*)d_in[4+12*L+0];
        const float* gb  = (const float*)d_in[4+12*L+1];
        const float* rw  = (const float*)d_in[4+12*L+2];
        const float* rb  = (const float*)d_in[4+12*L+3];
        const float* lg  = (const float*)d_in[4+12*L+4];
        const float* lb  = (const float*)d_in[4+12*L+5];
        const float* Wg  = (const float*)d_in[4+12*L+6];
        const float* bg  = (const float*)d_in[4+12*L+7];
        const float* asv = (const float*)d_in[4+12*L+8];
        const float* adv = (const float*)d_in[4+12*L+9];
        const float* aev = (const float*)d_in[4+12*L+10];
        const float* eww = (const float*)d_in[4+12*L+11];

        const float* xin  = (L == 0) ? x : nullptr;             // null -> g_xcur
        float*       xout = (L == 1) ? (float*)d_out : nullptr; // null -> g_xcur

        k_gemm_dual<<<1563,256>>>(xin, gw, rw, rb);
        k_gcn_ln<<<6250,256>>>(gb, lg, lb);
        k_gemm_gat<<<782,256>>>(Wg, asv, adv);
        k_ce<<<1,32>>>(eww, aev);
        k_gat_gather<<<6250,256>>>(bg, xout);
    }
}

// round 6
// speedup vs baseline: 1.4045x; 1.0495x over previous
#include <cuda_runtime.h>

#define NN 50000
#define EE 800000
#define FULL 0xffffffffu

// ---------------- scratch (static device globals; no allocs) ----------------
static __device__ float g_h[NN*64];      // GCN-transformed features
static __device__ float g_res[NN*64];    // residual branch
static __device__ float g_xln[NN*64];    // post-GCN layernorm output
static __device__ float g_xg[NN*64];     // GAT-transformed features
static __device__ float g_xcur[NN*64];   // layer-0 output
static __device__ float g_deg[NN];
static __device__ float g_dinv[NN];
static __device__ int   g_cnt[NN];       // in-degree counts (edges only)
static __device__ int   g_ps[NN];        // inclusive scan scratch
static __device__ int   g_blk[128];      // block sums
static __device__ int   g_blkoff[128];
static __device__ int   g_rowptr[NN+1];
static __device__ int   g_cur[NN];
static __device__ int   g_csrc[EE];      // CSR source node per slot
static __device__ int   g_cdst[EE];      // CSR dst node per slot
static __device__ float g_cw[EE];        // CSR gcn norm weight per slot
static __device__ float g_cea[EE];       // CSR edge_attr per slot
static __device__ float g_as[NN*4];
static __device__ float g_ad[NN*4];
static __device__ float g_ep[EE*4];      // exp(alpha) per CSR slot, 4 heads
static __device__ float g_ce[8];         // [0..3]=ce per head, [4]=mean(edge_attr)
static __device__ float g_easum;

// ---------------- helpers ----------------
__device__ __forceinline__ float siluf(float v) { return v * (1.f / (1.f + __expf(-v))); }
__device__ __forceinline__ float lrelu(float v) { return v >= 0.f ? v : 0.2f * v; }

// ---------------- GEMMs ----------------
// g_h = x@W0, g_res = x@W1 + b1. 32-row tile, 256 threads.
__global__ __launch_bounds__(256) void k_gemm_dual(
    const float* __restrict__ xin, const float* __restrict__ W0,
    const float* __restrict__ W1, const float* __restrict__ b1)
{
    const float* x = xin ? xin : g_xcur;
    __shared__ float xs[32*68];
    __shared__ float ws[2][64*68];
    int t = threadIdx.x;
    int row0 = blockIdx.x * 32;
    for (int i = t; i < 4096; i += 256) {
        int k = i >> 6, c = i & 63;
        ws[0][k*68+c] = W0[i];
        ws[1][k*68+c] = W1[i];
    }
    for (int i = t; i < 2048; i += 256) {
        int r = i >> 6, c = i & 63;
        xs[r*68+c] = (row0 + r < NN) ? x[(row0+r)*64 + c] : 0.f;
    }
    __syncthreads();
    int rg = t >> 4, g = t & 15, m = g >> 3, cb = (g & 7) * 8;
    const float* wp = ws[m];
    int r0 = rg*2, r1 = r0 + 1;
    float a0[8], a1[8];
    #pragma unroll
    for (int j = 0; j < 8; j++) { a0[j] = 0.f; a1[j] = 0.f; }
    #pragma unroll 16
    for (int k = 0; k < 64; k++) {
        float xv0 = xs[r0*68+k], xv1 = xs[r1*68+k];
        float w[8];
        *(float4*)&w[0] = *(const float4*)&wp[k*68+cb];
        *(float4*)&w[4] = *(const float4*)&wp[k*68+cb+4];
        #pragma unroll
        for (int j = 0; j < 8; j++) { a0[j] += xv0 * w[j]; a1[j] += xv1 * w[j]; }
    }
    float* y = m ? g_res : g_h;
    if (m) {
        #pragma unroll
        for (int j = 0; j < 8; j++) { float b = b1[cb+j]; a0[j] += b; a1[j] += b; }
    }
    if (row0 + r0 < NN) {
        *(float4*)&y[(row0+r0)*64+cb]   = *(float4*)&a0[0];
        *(float4*)&y[(row0+r0)*64+cb+4] = *(float4*)&a0[4];
    }
    if (row0 + r1 < NN) {
        *(float4*)&y[(row0+r1)*64+cb]   = *(float4*)&a1[0];
        *(float4*)&y[(row0+r1)*64+cb+4] = *(float4*)&a1[4];
    }
}

// g_xg = g_xln @ W ; fused attention dots g_as/g_ad. 64-row tile, 256 threads.
__global__ __launch_bounds__(256) void k_gemm_gat(
    const float* __restrict__ W,
    const float* __restrict__ asrc, const float* __restrict__ adst)
{
    __shared__ float xs[64*68];
    __shared__ float ws[64*68];
    int t = threadIdx.x;
    int row0 = blockIdx.x * 64;
    for (int i = t; i < 4096; i += 256) {
        int k = i >> 6, c = i & 63;
        ws[k*68+c] = W[i];
    }
    for (int i = t; i < 4096; i += 256) {
        int r = i >> 6, c = i & 63;
        xs[r*68+c] = (row0 + r < NN) ? g_xln[(row0+r)*64 + c] : 0.f;
    }
    __syncthreads();
    int rg = t >> 3, cb = (t & 7) * 8;
    int r0 = rg*2, r1 = r0 + 1;
    float a0[8], a1[8];
    #pragma unroll
    for (int j = 0; j < 8; j++) { a0[j] = 0.f; a1[j] = 0.f; }
    #pragma unroll 16
    for (int k = 0; k < 64; k++) {
        float xv0 = xs[r0*68+k], xv1 = xs[r1*68+k];
        float w[8];
        *(float4*)&w[0] = *(const float4*)&ws[k*68+cb];
        *(float4*)&w[4] = *(const float4*)&ws[k*68+cb+4];
        #pragma unroll
        for (int j = 0; j < 8; j++) { a0[j] += xv0 * w[j]; a1[j] += xv1 * w[j]; }
    }
    if (row0 + r0 < NN) {
        *(float4*)&g_xg[(row0+r0)*64+cb]   = *(float4*)&a0[0];
        *(float4*)&g_xg[(row0+r0)*64+cb+4] = *(float4*)&a0[4];
    }
    if (row0 + r1 < NN) {
        *(float4*)&g_xg[(row0+r1)*64+cb]   = *(float4*)&a1[0];
        *(float4*)&g_xg[(row0+r1)*64+cb+4] = *(float4*)&a1[4];
    }
    // fused attention dots: thread pair (t, t^1) covers one head (16 cols)
    float s0 = 0.f, s1 = 0.f, d0 = 0.f, d1 = 0.f;
    #pragma unroll
    for (int j = 0; j < 8; j++) {
        float av = asrc[cb+j], dv = adst[cb+j];
        s0 += a0[j]*av; d0 += a0[j]*dv;
        s1 += a1[j]*av; d1 += a1[j]*dv;
    }
    s0 += __shfl_xor_sync(FULL, s0, 1);
    s1 += __shfl_xor_sync(FULL, s1, 1);
    d0 += __shfl_xor_sync(FULL, d0, 1);
    d1 += __shfl_xor_sync(FULL, d1, 1);
    if ((t & 1) == 0) {
        int hh = cb >> 4;
        if (row0 + r0 < NN) { g_as[(row0+r0)*4+hh] = s0; g_ad[(row0+r0)*4+hh] = d0; }
        if (row0 + r1 < NN) { g_as[(row0+r1)*4+hh] = s1; g_ad[(row0+r1)*4+hh] = d1; }
    }
}

// ---------------- graph setup (once per call) ----------------
__global__ void k_init() {
    int i = blockIdx.x*256 + threadIdx.x;
    if (i < NN) { g_deg[i] = 1.f; g_cnt[i] = 0; }
    if (i == 0) g_easum = 0.f;
}
__global__ void k_easum(const float* __restrict__ ea) {
    __shared__ float ss[8];
    float sum = 0.f;
    for (int i = blockIdx.x*blockDim.x + threadIdx.x; i < EE; i += gridDim.x*blockDim.x)
        sum += ea[i];
    #pragma unroll
    for (int o = 16; o; o >>= 1) sum += __shfl_xor_sync(FULL, sum, o);
    if ((threadIdx.x & 31) == 0) ss[threadIdx.x >> 5] = sum;
    __syncthreads();
    if (threadIdx.x < 8) {
        float v = ss[threadIdx.x];
        #pragma unroll
        for (int o = 4; o; o >>= 1) v += __shfl_xor_sync(0xffu, v, o);
        if (threadIdx.x == 0) atomicAdd(&g_easum, v);
    }
}
__global__ void k_deg_edge(const int* __restrict__ ei, const float* __restrict__ ew) {
    int e = blockIdx.x*256 + threadIdx.x;
    int d = ei[EE+e];
    atomicAdd(&g_deg[d], ew[e]);
    atomicAdd(&g_cnt[d], 1);
}
__global__ __launch_bounds__(512) void k_scan1() {
    __shared__ int sm[512];
    int t = threadIdx.x;
    int idx = blockIdx.x*512 + t;
    if (idx < NN) g_dinv[idx] = rsqrtf(g_deg[idx]);
    int c = (idx < NN) ? g_cnt[idx] : 0;
    sm[t] = c; __syncthreads();
    #pragma unroll
    for (int off = 1; off < 512; off <<= 1) {
        int v = (t >= off) ? sm[t-off] : 0;
        __syncthreads();
        sm[t] += v;
        __syncthreads();
    }
    if (idx < NN) g_ps[idx] = sm[t];
    if (t == 511) g_blk[blockIdx.x] = sm[511];
}
__global__ void k_scan2(int nblk) {
    if (threadIdx.x == 0) {
        int run = 0;
        for (int i = 0; i < nblk; i++) { g_blkoff[i] = run; run += g_blk[i]; }
    }
}
__global__ __launch_bounds__(512) void k_scan3() {
    int idx = blockIdx.x*512 + threadIdx.x;
    if (idx < NN) {
        g_rowptr[idx+1] = g_ps[idx] + g_blkoff[blockIdx.x];
        g_cur[idx] = 0;
        if (idx == 0) g_rowptr[0] = 0;
    }
}
__global__ void k_fill(const int* __restrict__ ei, const float* __restrict__ ew,
                       const float* __restrict__ ea) {
    int e = blockIdx.x*256 + threadIdx.x;
    int s = ei[e], d = ei[EE+e];
    int pos = g_rowptr[d] + atomicAdd(&g_cur[d], 1);
    g_csrc[pos] = s;
    g_cdst[pos] = d;
    g_cw[pos]   = g_dinv[s] * ew[e] * g_dinv[d];
    g_cea[pos]  = ea[e];
}

// ---------------- GCN gather + silu + residual + LN (warp per node) ----------------
__global__ __launch_bounds__(256) void k_gcn_ln(
    const float* __restrict__ gb, const float* __restrict__ lg, const float* __restrict__ lb)
{
    int row = blockIdx.x*8 + (threadIdx.x >> 5);
    if (row >= NN) return;
    int lane = threadIdx.x & 31;
    int start = g_rowptr[row], end = g_rowptr[row+1];
    float dv = g_dinv[row];
    float acc0 = g_h[row*64+lane]    * dv * dv;
    float acc1 = g_h[row*64+32+lane] * dv * dv;
    for (int base = start; base < end; base += 32) {
        int j = base + lane;
        int ms  = (j < end) ? g_csrc[j] : 0;
        float mw = (j < end) ? g_cw[j] : 0.f;
        int n = min(32, end - base);
        for (int k = 0; k < n; k++) {
            int s  = __shfl_sync(FULL, ms, k);
            float w = __shfl_sync(FULL, mw, k);
            acc0 += w * __ldg(&g_h[s*64+lane]);
            acc1 += w * __ldg(&g_h[s*64+32+lane]);
        }
    }
    float v0 = siluf(acc0 + gb[lane])    + g_res[row*64+lane];
    float v1 = siluf(acc1 + gb[lane+32]) + g_res[row*64+32+lane];
    float sum = v0 + v1;
    #pragma unroll
    for (int o = 16; o; o >>= 1) sum += __shfl_xor_sync(FULL, sum, o);
    float mu = sum * (1.f/64.f);
    float d0 = v0 - mu, d1 = v1 - mu;
    float vs = d0*d0 + d1*d1;
    #pragma unroll
    for (int o = 16; o; o >>= 1) vs += __shfl_xor_sync(FULL, vs, o);
    float inv = rsqrtf(vs * (1.f/64.f) + 1e-5f);
    g_xln[row*64+lane]    = d0 * inv * lg[lane]    + lb[lane];
    g_xln[row*64+32+lane] = d1 * inv * lg[lane+32] + lb[lane+32];
}

// ---------------- GAT ----------------
// ce[h] = sum_c We[h*16+c]*a_e[h*16+c]; ce[4] = mean(edge_attr)
__global__ void k_ce(const float* __restrict__ eww, const float* __restrict__ ae) {
    int lane = threadIdx.x;
    float p0 = eww[lane]*ae[lane];
    float p1 = eww[lane+32]*ae[lane+32];
    #pragma unroll
    for (int o = 8; o; o >>= 1) {
        p0 += __shfl_xor_sync(FULL, p0, o);
        p1 += __shfl_xor_sync(FULL, p1, o);
    }
    if ((lane & 15) == 0) {
        g_ce[lane >> 4]       = p0;
        g_ce[2 + (lane >> 4)] = p1;
    }
    if (lane == 0) g_ce[4] = g_easum * (1.f / EE);
}
// CSR-ordered edge-parallel: exp(alpha) written linearly
__global__ void k_gatA() {
    int e = blockIdx.x*256 + threadIdx.x;   // CSR slot
    int s = g_csrc[e], d = g_cdst[e];
    float eav = g_cea[e];
    float4 av = *(const float4*)&g_as[s*4];
    float4 dv = *(const float4*)&g_ad[d*4];
    float4 ce = *(const float4*)&g_ce[0];
    float4 p;
    p.x = __expf(fminf(lrelu(av.x + dv.x + eav*ce.x), 70.f));
    p.y = __expf(fminf(lrelu(av.y + dv.y + eav*ce.y), 70.f));
    p.z = __expf(fminf(lrelu(av.z + dv.z + eav*ce.z), 70.f));
    p.w = __expf(fminf(lrelu(av.w + dv.w + eav*ce.w), 70.f));
    *(float4*)&g_ep[e*4] = p;
}
// warp-per-node: weighted gather with inline softmax denominator + silu + skip
__global__ __launch_bounds__(256) void k_gat_gather(
    const float* __restrict__ bg, float* __restrict__ xout)
{
    int row = blockIdx.x*8 + (threadIdx.x >> 5);
    if (row >= NN) return;
    int lane = threadIdx.x & 31;
    int start = g_rowptr[row], end = g_rowptr[row+1];
    // self-loop exp(alpha)
    float4 av = *(const float4*)&g_as[row*4];
    float4 dv = *(const float4*)&g_ad[row*4];
    float4 ce = *(const float4*)&g_ce[0];
    float cm = g_ce[4];
    float4 ps;
    ps.x = __expf(fminf(lrelu(av.x + dv.x + cm*ce.x), 70.f));
    ps.y = __expf(fminf(lrelu(av.y + dv.y + cm*ce.y), 70.f));
    ps.z = __expf(fminf(lrelu(av.z + dv.z + cm*ce.z), 70.f));
    ps.w = __expf(fminf(lrelu(av.w + dv.w + cm*ce.w), 70.f));
    float pa_self = (lane < 16) ? ps.x : ps.y;
    float pb_self = (lane < 16) ? ps.z : ps.w;
    float acc0 = g_xg[row*64+lane]    * pa_self;
    float acc1 = g_xg[row*64+32+lane] * pb_self;
    float sa = pa_self, sb = pb_self;    // per-lane softmax denominators
    for (int base = start; base < end; base += 32) {
        int j = base + lane;
        int ms = (j < end) ? g_csrc[j] : 0;
        float4 mp = (j < end) ? *(const float4*)&g_ep[j*4] : make_float4(0.f,0.f,0.f,0.f);
        int n = min(32, end - base);
        for (int k = 0; k < n; k++) {
            int s = __shfl_sync(FULL, ms, k);
            float p0 = __shfl_sync(FULL, mp.x, k);
            float p1 = __shfl_sync(FULL, mp.y, k);
            float p2 = __shfl_sync(FULL, mp.z, k);
            float p3 = __shfl_sync(FULL, mp.w, k);
            float pa = (lane < 16) ? p0 : p1;
            float pb = (lane < 16) ? p2 : p3;
            acc0 += pa * __ldg(&g_xg[s*64+lane]);
            acc1 += pb * __ldg(&g_xg[s*64+32+lane]);
            sa += pa;
            sb += pb;
        }
    }
    float ia = 1.f/(sa + 1e-16f);
    float ib = 1.f/(sb + 1e-16f);
    float* o = xout ? xout : g_xcur;
    o[row*64+lane]    = siluf(acc0*ia + bg[lane])    + g_xln[row*64+lane];
    o[row*64+32+lane] = siluf(acc1*ib + bg[lane+32]) + g_xln[row*64+32+lane];
}

// ---------------- launch ----------------
extern "C" void kernel_launch(void* const* d_in, const int* in_sizes, int n_in,
                              void* d_out, int out_size) {
    (void)in_sizes; (void)n_in; (void)out_size;
    const float* x  = (const float*)d_in[0];
    const int*   ei = (const int*)  d_in[1];
    const float* ew = (const float*)d_in[2];
    const float* ea = (const float*)d_in[3];

    // graph-structure setup (layer-independent)
    k_init<<<196,256>>>();
    k_easum<<<1024,256>>>(ea);
    k_deg_edge<<<3125,256>>>(ei, ew);
    k_scan1<<<98,512>>>();
    k_scan2<<<1,32>>>(98);
    k_scan3<<<98,512>>>();
    k_fill<<<3125,256>>>(ei, ew, ea);

    for (int L = 0; L < 2; L++) {
        const float* gw  = (const float*)d_in[4+12*L+0];
        const float* gb  = (const float*)d_in[4+12*L+1];
        const float* rw  = (const float*)d_in[4+12*L+2];
        const float* rb  = (const float*)d_in[4+12*L+3];
        const float* lg  = (const float*)d_in[4+12*L+4];
        const float* lb  = (const float*)d_in[4+12*L+5];
        const float* Wg  = (const float*)d_in[4+12*L+6];
        const float* bg  = (const float*)d_in[4+12*L+7];
        const float* asv = (const float*)d_in[4+12*L+8];
        const float* adv = (const float*)d_in[4+12*L+9];
        const float* aev = (const float*)d_in[4+12*L+10];
        const float* eww = (const float*)d_in[4+12*L+11];

        const float* xin  = (L == 0) ? x : nullptr;             // null -> g_xcur
        float*       xout = (L == 1) ? (float*)d_out : nullptr; // null -> g_xcur

        k_gemm_dual<<<1563,256>>>(xin, gw, rw, rb);
        k_gcn_ln<<<6250,256>>>(gb, lg, lb);
        k_gemm_gat<<<782,256>>>(Wg, asv, adv);
        k_ce<<<1,32>>>(eww, aev);
        k_gatA<<<3125,256>>>();
        k_gat_gather<<<6250,256>>>(bg, xout);
    }
}

// round 7
// speedup vs baseline: 1.6318x; 1.1618x over previous
#include <cuda_runtime.h>

#define NN 50000
#define EE 800000
#define FULL 0xffffffffu

// ---------------- scratch (static device globals; no allocs) ----------------
static __device__ float g_h[NN*64];      // GCN-transformed features
static __device__ float g_res[NN*64];    // residual branch
static __device__ float g_xln[NN*64];    // post-GCN layernorm output
static __device__ float g_xg[NN*64];     // GAT-transformed features
static __device__ float g_xcur[NN*64];   // layer-0 output
static __device__ float g_deg[NN];
static __device__ float g_dinv[NN];
static __device__ int   g_cnt[NN];       // in-degree counts (edges only)
static __device__ int   g_ps[NN];        // inclusive scan scratch
static __device__ int   g_blk[128];      // block sums
static __device__ int   g_blkoff[128];
static __device__ int   g_rowptr[NN+1];
static __device__ int   g_cur[NN];
static __device__ int2  g_cpk[EE];       // CSR slot -> (src, gcn-weight bits)
static __device__ int   g_cdst[EE];      // CSR dst node per slot
static __device__ float g_cea[EE];       // CSR edge_attr per slot
static __device__ float g_as[NN*4];
static __device__ float g_ad[NN*4];
static __device__ float g_ep[EE*4];      // exp(alpha) per CSR slot, 4 heads
static __device__ float g_ce[8];         // [0..3]=ce per head, [4]=mean(edge_attr)
static __device__ float g_easum;

// ---------------- helpers ----------------
__device__ __forceinline__ float siluf(float v) { return v * (1.f / (1.f + __expf(-v))); }
__device__ __forceinline__ float lrelu(float v) { return v >= 0.f ? v : 0.2f * v; }

// ---------------- GEMMs ----------------
// g_h = x@W0, g_res = x@W1 + b1. 32-row tile, 256 threads.
__global__ __launch_bounds__(256) void k_gemm_dual(
    const float* __restrict__ xin, const float* __restrict__ W0,
    const float* __restrict__ W1, const float* __restrict__ b1)
{
    const float* x = xin ? xin : g_xcur;
    __shared__ float xs[32*68];
    __shared__ float ws[2][64*68];
    int t = threadIdx.x;
    int row0 = blockIdx.x * 32;
    for (int i = t; i < 4096; i += 256) {
        int k = i >> 6, c = i & 63;
        ws[0][k*68+c] = W0[i];
        ws[1][k*68+c] = W1[i];
    }
    for (int i = t; i < 2048; i += 256) {
        int r = i >> 6, c = i & 63;
        xs[r*68+c] = (row0 + r < NN) ? x[(row0+r)*64 + c] : 0.f;
    }
    __syncthreads();
    int rg = t >> 4, g = t & 15, m = g >> 3, cb = (g & 7) * 8;
    const float* wp = ws[m];
    int r0 = rg*2, r1 = r0 + 1;
    float a0[8], a1[8];
    #pragma unroll
    for (int j = 0; j < 8; j++) { a0[j] = 0.f; a1[j] = 0.f; }
    #pragma unroll 16
    for (int k = 0; k < 64; k++) {
        float xv0 = xs[r0*68+k], xv1 = xs[r1*68+k];
        float w[8];
        *(float4*)&w[0] = *(const float4*)&wp[k*68+cb];
        *(float4*)&w[4] = *(const float4*)&wp[k*68+cb+4];
        #pragma unroll
        for (int j = 0; j < 8; j++) { a0[j] += xv0 * w[j]; a1[j] += xv1 * w[j]; }
    }
    float* y = m ? g_res : g_h;
    if (m) {
        #pragma unroll
        for (int j = 0; j < 8; j++) { float b = b1[cb+j]; a0[j] += b; a1[j] += b; }
    }
    if (row0 + r0 < NN) {
        *(float4*)&y[(row0+r0)*64+cb]   = *(float4*)&a0[0];
        *(float4*)&y[(row0+r0)*64+cb+4] = *(float4*)&a0[4];
    }
    if (row0 + r1 < NN) {
        *(float4*)&y[(row0+r1)*64+cb]   = *(float4*)&a1[0];
        *(float4*)&y[(row0+r1)*64+cb+4] = *(float4*)&a1[4];
    }
}

// g_xg = g_xln @ W ; fused attention dots g_as/g_ad. 64-row tile, 256 threads.
__global__ __launch_bounds__(256) void k_gemm_gat(
    const float* __restrict__ W,
    const float* __restrict__ asrc, const float* __restrict__ adst)
{
    __shared__ float xs[64*68];
    __shared__ float ws[64*68];
    int t = threadIdx.x;
    int row0 = blockIdx.x * 64;
    for (int i = t; i < 4096; i += 256) {
        int k = i >> 6, c = i & 63;
        ws[k*68+c] = W[i];
    }
    for (int i = t; i < 4096; i += 256) {
        int r = i >> 6, c = i & 63;
        xs[r*68+c] = (row0 + r < NN) ? g_xln[(row0+r)*64 + c] : 0.f;
    }
    __syncthreads();
    int rg = t >> 3, cb = (t & 7) * 8;
    int r0 = rg*2, r1 = r0 + 1;
    float a0[8], a1[8];
    #pragma unroll
    for (int j = 0; j < 8; j++) { a0[j] = 0.f; a1[j] = 0.f; }
    #pragma unroll 16
    for (int k = 0; k < 64; k++) {
        float xv0 = xs[r0*68+k], xv1 = xs[r1*68+k];
        float w[8];
        *(float4*)&w[0] = *(const float4*)&ws[k*68+cb];
        *(float4*)&w[4] = *(const float4*)&ws[k*68+cb+4];
        #pragma unroll
        for (int j = 0; j < 8; j++) { a0[j] += xv0 * w[j]; a1[j] += xv1 * w[j]; }
    }
    if (row0 + r0 < NN) {
        *(float4*)&g_xg[(row0+r0)*64+cb]   = *(float4*)&a0[0];
        *(float4*)&g_xg[(row0+r0)*64+cb+4] = *(float4*)&a0[4];
    }
    if (row0 + r1 < NN) {
        *(float4*)&g_xg[(row0+r1)*64+cb]   = *(float4*)&a1[0];
        *(float4*)&g_xg[(row0+r1)*64+cb+4] = *(float4*)&a1[4];
    }
    // fused attention dots: thread pair (t, t^1) covers one head (16 cols)
    float s0 = 0.f, s1 = 0.f, d0 = 0.f, d1 = 0.f;
    #pragma unroll
    for (int j = 0; j < 8; j++) {
        float av = asrc[cb+j], dv = adst[cb+j];
        s0 += a0[j]*av; d0 += a0[j]*dv;
        s1 += a1[j]*av; d1 += a1[j]*dv;
    }
    s0 += __shfl_xor_sync(FULL, s0, 1);
    s1 += __shfl_xor_sync(FULL, s1, 1);
    d0 += __shfl_xor_sync(FULL, d0, 1);
    d1 += __shfl_xor_sync(FULL, d1, 1);
    if ((t & 1) == 0) {
        int hh = cb >> 4;
        if (row0 + r0 < NN) { g_as[(row0+r0)*4+hh] = s0; g_ad[(row0+r0)*4+hh] = d0; }
        if (row0 + r1 < NN) { g_as[(row0+r1)*4+hh] = s1; g_ad[(row0+r1)*4+hh] = d1; }
    }
}

// ---------------- graph setup (once per call) ----------------
__global__ void k_init() {
    int i = blockIdx.x*256 + threadIdx.x;
    if (i < NN) { g_deg[i] = 1.f; g_cnt[i] = 0; }
    if (i == 0) g_easum = 0.f;
}
__global__ void k_easum(const float* __restrict__ ea) {
    __shared__ float ss[8];
    float sum = 0.f;
    for (int i = blockIdx.x*blockDim.x + threadIdx.x; i < EE; i += gridDim.x*blockDim.x)
        sum += ea[i];
    #pragma unroll
    for (int o = 16; o; o >>= 1) sum += __shfl_xor_sync(FULL, sum, o);
    if ((threadIdx.x & 31) == 0) ss[threadIdx.x >> 5] = sum;
    __syncthreads();
    if (threadIdx.x < 8) {
        float v = ss[threadIdx.x];
        #pragma unroll
        for (int o = 4; o; o >>= 1) v += __shfl_xor_sync(0xffu, v, o);
        if (threadIdx.x == 0) atomicAdd(&g_easum, v);
    }
}
__global__ void k_deg_edge(const int* __restrict__ ei, const float* __restrict__ ew) {
    int e = blockIdx.x*256 + threadIdx.x;
    int d = ei[EE+e];
    atomicAdd(&g_deg[d], ew[e]);
    atomicAdd(&g_cnt[d], 1);
}
__global__ __launch_bounds__(512) void k_scan1() {
    __shared__ int sm[512];
    int t = threadIdx.x;
    int idx = blockIdx.x*512 + t;
    if (idx < NN) g_dinv[idx] = rsqrtf(g_deg[idx]);
    int c = (idx < NN) ? g_cnt[idx] : 0;
    sm[t] = c; __syncthreads();
    #pragma unroll
    for (int off = 1; off < 512; off <<= 1) {
        int v = (t >= off) ? sm[t-off] : 0;
        __syncthreads();
        sm[t] += v;
        __syncthreads();
    }
    if (idx < NN) g_ps[idx] = sm[t];
    if (t == 511) g_blk[blockIdx.x] = sm[511];
}
__global__ void k_scan2(int nblk) {
    if (threadIdx.x == 0) {
        int run = 0;
        for (int i = 0; i < nblk; i++) { g_blkoff[i] = run; run += g_blk[i]; }
    }
}
__global__ __launch_bounds__(512) void k_scan3() {
    int idx = blockIdx.x*512 + threadIdx.x;
    if (idx < NN) {
        g_rowptr[idx+1] = g_ps[idx] + g_blkoff[blockIdx.x];
        g_cur[idx] = 0;
        if (idx == 0) g_rowptr[0] = 0;
    }
}
__global__ void k_fill(const int* __restrict__ ei, const float* __restrict__ ew,
                       const float* __restrict__ ea) {
    int e = blockIdx.x*256 + threadIdx.x;
    int s = ei[e], d = ei[EE+e];
    int pos = g_rowptr[d] + atomicAdd(&g_cur[d], 1);
    g_cpk[pos] = make_int2(s, __float_as_int(g_dinv[s] * ew[e] * g_dinv[d]));
    g_cdst[pos] = d;
    g_cea[pos]  = ea[e];
}

// -------- GCN gather + silu + residual + LN (warp per node, half-warp per edge) -----
__global__ __launch_bounds__(256) void k_gcn_ln(
    const float* __restrict__ gb, const float* __restrict__ lg, const float* __restrict__ lb)
{
    int row = blockIdx.x*8 + (threadIdx.x >> 5);
    if (row >= NN) return;
    int lane = threadIdx.x & 31;
    int q = lane & 15, half = lane >> 4;
    int start = g_rowptr[row], end = g_rowptr[row+1];
    float4 acc = make_float4(0.f, 0.f, 0.f, 0.f);
    if (half == 0) {
        float dv = g_dinv[row];
        float ss = dv * dv;
        float4 hv = *(const float4*)&g_h[row*64 + q*4];
        acc.x = hv.x*ss; acc.y = hv.y*ss; acc.z = hv.z*ss; acc.w = hv.w*ss;
    }
    for (int j = start + half; j < end; j += 2) {
        int2 pk = __ldg(&g_cpk[j]);
        float w = __int_as_float(pk.y);
        float4 v = *(const float4*)&g_h[pk.x*64 + q*4];
        acc.x += w*v.x; acc.y += w*v.y; acc.z += w*v.z; acc.w += w*v.w;
    }
    acc.x += __shfl_xor_sync(FULL, acc.x, 16);
    acc.y += __shfl_xor_sync(FULL, acc.y, 16);
    acc.z += __shfl_xor_sync(FULL, acc.z, 16);
    acc.w += __shfl_xor_sync(FULL, acc.w, 16);
    // both halves now hold the full sums; compute LN redundantly, half 0 stores
    float4 gb4 = *(const float4*)&gb[q*4];
    float4 rs4 = *(const float4*)&g_res[row*64 + q*4];
    float4 v;
    v.x = siluf(acc.x + gb4.x) + rs4.x;
    v.y = siluf(acc.y + gb4.y) + rs4.y;
    v.z = siluf(acc.z + gb4.z) + rs4.z;
    v.w = siluf(acc.w + gb4.w) + rs4.w;
    float sum = v.x + v.y + v.z + v.w;
    #pragma unroll
    for (int o = 8; o; o >>= 1) sum += __shfl_xor_sync(FULL, sum, o);
    float mu = sum * (1.f/64.f);
    float4 d;
    d.x = v.x - mu; d.y = v.y - mu; d.z = v.z - mu; d.w = v.w - mu;
    float vs = d.x*d.x + d.y*d.y + d.z*d.z + d.w*d.w;
    #pragma unroll
    for (int o = 8; o; o >>= 1) vs += __shfl_xor_sync(FULL, vs, o);
    float inv = rsqrtf(vs * (1.f/64.f) + 1e-5f);
    if (half == 0) {
        float4 lg4 = *(const float4*)&lg[q*4];
        float4 lb4 = *(const float4*)&lb[q*4];
        float4 o4;
        o4.x = d.x*inv*lg4.x + lb4.x;
        o4.y = d.y*inv*lg4.y + lb4.y;
        o4.z = d.z*inv*lg4.z + lb4.z;
        o4.w = d.w*inv*lg4.w + lb4.w;
        *(float4*)&g_xln[row*64 + q*4] = o4;
    }
}

// ---------------- GAT ----------------
// ce[h] = sum_c We[h*16+c]*a_e[h*16+c]; ce[4] = mean(edge_attr)
__global__ void k_ce(const float* __restrict__ eww, const float* __restrict__ ae) {
    int lane = threadIdx.x;
    float p0 = eww[lane]*ae[lane];
    float p1 = eww[lane+32]*ae[lane+32];
    #pragma unroll
    for (int o = 8; o; o >>= 1) {
        p0 += __shfl_xor_sync(FULL, p0, o);
        p1 += __shfl_xor_sync(FULL, p1, o);
    }
    if ((lane & 15) == 0) {
        g_ce[lane >> 4]       = p0;
        g_ce[2 + (lane >> 4)] = p1;
    }
    if (lane == 0) g_ce[4] = g_easum * (1.f / EE);
}
// CSR-ordered edge-parallel: exp(alpha) written linearly
__global__ void k_gatA() {
    int e = blockIdx.x*256 + threadIdx.x;   // CSR slot
    int s = g_cpk[e].x, d = g_cdst[e];
    float eav = g_cea[e];
    float4 av = *(const float4*)&g_as[s*4];
    float4 dv = *(const float4*)&g_ad[d*4];
    float4 ce = *(const float4*)&g_ce[0];
    float4 p;
    p.x = __expf(fminf(lrelu(av.x + dv.x + eav*ce.x), 70.f));
    p.y = __expf(fminf(lrelu(av.y + dv.y + eav*ce.y), 70.f));
    p.z = __expf(fminf(lrelu(av.z + dv.z + eav*ce.z), 70.f));
    p.w = __expf(fminf(lrelu(av.w + dv.w + eav*ce.w), 70.f));
    *(float4*)&g_ep[e*4] = p;
}
// warp-per-node, half-warp per edge: gather + inline softmax denom + silu + skip
__global__ __launch_bounds__(256) void k_gat_gather(
    const float* __restrict__ bg, float* __restrict__ xout)
{
    int row = blockIdx.x*8 + (threadIdx.x >> 5);
    if (row >= NN) return;
    int lane = threadIdx.x & 31;
    int q = lane & 15, half = lane >> 4;
    int h = q >> 2;                          // head of this lane's 4 columns
    int start = g_rowptr[row], end = g_rowptr[row+1];
    // self-loop exp(alpha)
    float4 av = *(const float4*)&g_as[row*4];
    float4 dv = *(const float4*)&g_ad[row*4];
    float4 ce = *(const float4*)&g_ce[0];
    float cm = g_ce[4];
    float4 ps;
    ps.x = __expf(fminf(lrelu(av.x + dv.x + cm*ce.x), 70.f));
    ps.y = __expf(fminf(lrelu(av.y + dv.y + cm*ce.y), 70.f));
    ps.z = __expf(fminf(lrelu(av.z + dv.z + cm*ce.z), 70.f));
    ps.w = __expf(fminf(lrelu(av.w + dv.w + cm*ce.w), 70.f));
    float p_self = (q < 8) ? ((q < 4) ? ps.x : ps.y) : ((q < 12) ? ps.z : ps.w);
    float4 acc = make_float4(0.f, 0.f, 0.f, 0.f);
    float sa = 0.f;
    if (half == 0) {
        float4 xv = *(const float4*)&g_xg[row*64 + q*4];
        acc.x = xv.x*p_self; acc.y = xv.y*p_self; acc.z = xv.z*p_self; acc.w = xv.w*p_self;
        sa = p_self;
    }
    for (int j = start + half; j < end; j += 2) {
        int s = __ldg(&g_cpk[j]).x;
        float p = __ldg(&g_ep[j*4 + h]);
        float4 v = *(const float4*)&g_xg[s*64 + q*4];
        acc.x += p*v.x; acc.y += p*v.y; acc.z += p*v.z; acc.w += p*v.w;
        sa += p;
    }
    acc.x += __shfl_xor_sync(FULL, acc.x, 16);
    acc.y += __shfl_xor_sync(FULL, acc.y, 16);
    acc.z += __shfl_xor_sync(FULL, acc.z, 16);
    acc.w += __shfl_xor_sync(FULL, acc.w, 16);
    sa    += __shfl_xor_sync(FULL, sa, 16);
    if (half == 0) {
        float ia = 1.f / (sa + 1e-16f);
        float4 bg4 = *(const float4*)&bg[q*4];
        float4 xl4 = *(const float4*)&g_xln[row*64 + q*4];
        float* o = xout ? xout : g_xcur;
        float4 o4;
        o4.x = siluf(acc.x*ia + bg4.x) + xl4.x;
        o4.y = siluf(acc.y*ia + bg4.y) + xl4.y;
        o4.z = siluf(acc.z*ia + bg4.z) + xl4.z;
        o4.w = siluf(acc.w*ia + bg4.w) + xl4.w;
        *(float4*)&o[row*64 + q*4] = o4;
    }
}

// ---------------- launch ----------------
extern "C" void kernel_launch(void* const* d_in, const int* in_sizes, int n_in,
                              void* d_out, int out_size) {
    (void)in_sizes; (void)n_in; (void)out_size;
    const float* x  = (const float*)d_in[0];
    const int*   ei = (const int*)  d_in[1];
    const float* ew = (const float*)d_in[2];
    const float* ea = (const float*)d_in[3];

    // graph-structure setup (layer-independent)
    k_init<<<196,256>>>();
    k_easum<<<1024,256>>>(ea);
    k_deg_edge<<<3125,256>>>(ei, ew);
    k_scan1<<<98,512>>>();
    k_scan2<<<1,32>>>(98);
    k_scan3<<<98,512>>>();
    k_fill<<<3125,256>>>(ei, ew, ea);

    for (int L = 0; L < 2; L++) {
        const float* gw  = (const float*)d_in[4+12*L+0];
        const float* gb  = (const float*)d_in[4+12*L+1];
        const float* rw  = (const float*)d_in[4+12*L+2];
        const float* rb  = (const float*)d_in[4+12*L+3];
        const float* lg  = (const float*)d_in[4+12*L+4];
        const float* lb  = (const float*)d_in[4+12*L+5];
        const float* Wg  = (const float*)d_in[4+12*L+6];
        const float* bg  = (const float*)d_in[4+12*L+7];
        const float* asv = (const float*)d_in[4+12*L+8];
        const float* adv = (const float*)d_in[4+12*L+9];
        const float* aev = (const float*)d_in[4+12*L+10];
        const float* eww = (const float*)d_in[4+12*L+11];

        const float* xin  = (L == 0) ? x : nullptr;             // null -> g_xcur
        float*       xout = (L == 1) ? (float*)d_out : nullptr; // null -> g_xcur

        k_gemm_dual<<<1563,256>>>(xin, gw, rw, rb);
        k_gcn_ln<<<6250,256>>>(gb, lg, lb);
        k_gemm_gat<<<782,256>>>(Wg, asv, adv);
        k_ce<<<1,32>>>(eww, aev);
        k_gatA<<<3125,256>>>();
        k_gat_gather<<<6250,256>>>(bg, xout);
    }
}